// round 13
// baseline (speedup 1.0000x reference)
#include <cuda_runtime.h>
#include <cuda_bf16.h>
#include <math.h>

// Problem constants
#define BATCH   512
#define DIM     256
#define NTREES  512
#define DEPTH   6
#define UNITS   3
#define NLEAVES 64
#define NCOLS   (NTREES * DEPTH)   // 3072 sparsemax columns
#define MAXC    64                 // max sparsemax support per column (padded)
#define BT      128                // forest batch tile (4 b per thread)
#define NT      8                  // forest tree tile

// -------- device scratch (no dynamic allocation allowed) --------
__device__ float  g_xT[DIM * BATCH];       // transposed x: (DIM, BATCH)
__device__ float  g_fslT[NCOLS * DIM];     // transposed fsl: (col, i)
__device__ int    g_nnz[NCOLS];            // PADDED support size (multiple of 2)
__device__ float2 g_sel[NCOLS * MAXC];     // interleaved (idx*BATCH as int bits, weight)
__device__ float  g_gate[NCOLS * BATCH];   // gate values, layout (col, b)

// ============================================================================
// Kernel 0: float4 tiled transposes. 32x32 tiles, 256 threads:
// 1 LDG.128 + 4 STS + 4 LDS + 1 STG.128 per thread, bank-conflict-free.
//  blocks [0, 768): fsl (256 i, 3072 col) -> fslT (col, i).
//  blocks [768, 896): x (512 b, 256 i)    -> xT (i, b).
// ============================================================================
__global__ void __launch_bounds__(256)
transpose_kernel(const float* __restrict__ x,
                 const float* __restrict__ fsl)
{
    __shared__ float s[32][33];
    const int bid = blockIdx.x;
    const int t   = threadIdx.x;
    const int row = t >> 3;       // 0..31
    const int c4  = t & 7;        // 0..7

    const float* src;
    float*       dst;
    int src_stride, dst_stride, r0_in, c0_in;

    if (bid < 768) {
        const int it = bid / 96;
        const int ct = bid % 96;
        src = fsl;   src_stride = NCOLS;  r0_in = it * 32; c0_in = ct * 32;
        dst = g_fslT; dst_stride = DIM;
    } else {
        const int tt = bid - 768;
        const int bt = tt & 15;
        const int it = tt >> 4;
        src = x;     src_stride = DIM;    r0_in = bt * 32; c0_in = it * 32;
        dst = g_xT;  dst_stride = BATCH;
    }

    float4 v = *(const float4*)(src + (size_t)(r0_in + row) * src_stride + c0_in + c4 * 4);
    s[row][c4 * 4 + 0] = v.x;
    s[row][c4 * 4 + 1] = v.y;
    s[row][c4 * 4 + 2] = v.z;
    s[row][c4 * 4 + 3] = v.w;
    __syncthreads();

    float4 w;
    w.x = s[c4 * 4 + 0][row];
    w.y = s[c4 * 4 + 1][row];
    w.z = s[c4 * 4 + 2][row];
    w.w = s[c4 * 4 + 3][row];
    *(float4*)(dst + (size_t)(c0_in + row) * dst_stride + r0_in + c4 * 4) = w;
}

// ============================================================================
// Kernel 1: sparsemax, one warp per column, coalesced fslT loads.
// 384 blocks x 256 threads, warp-level only. Michelot warm-started at
// tau0 = max(z)-1 (valid: tau* >= zmax-1). Output padded to multiple of 2.
// ============================================================================
__global__ void __launch_bounds__(256)
sparsemax_kernel()
{
    const int warp = threadIdx.x >> 5;
    const int lane = threadIdx.x & 31;
    const int col  = blockIdx.x * 8 + warp;

    float z[8];
    #pragma unroll
    for (int j = 0; j < 8; j++)
        z[j] = g_fslT[col * DIM + j * 32 + lane];

    float m = z[0];
    #pragma unroll
    for (int j = 1; j < 8; j++) m = fmaxf(m, z[j]);
    #pragma unroll
    for (int o = 16; o > 0; o >>= 1)
        m = fmaxf(m, __shfl_xor_sync(0xffffffffu, m, o));
    float tau = m - 1.0f;

    int k_prev = -1;
    #pragma unroll 1
    for (int it = 0; it < 16; it++) {
        float s = 0.0f;
        int   k = 0;
        #pragma unroll
        for (int j = 0; j < 8; j++)
            if (z[j] > tau) { s += z[j]; k++; }
        #pragma unroll
        for (int o = 16; o > 0; o >>= 1)
            s += __shfl_xor_sync(0xffffffffu, s, o);
        k = __reduce_add_sync(0xffffffffu, k);
        if (k == k_prev) break;
        k_prev = k;
        tau = (s - 1.0f) / (float)k;
    }

    int base = 0;
    #pragma unroll
    for (int j = 0; j < 8; j++) {
        const bool nz = (z[j] > tau);
        const unsigned mm = __ballot_sync(0xffffffffu, nz);
        if (nz) {
            int pos = base + __popc(mm & ((1u << lane) - 1u));
            if (pos < MAXC)
                g_sel[col * MAXC + pos] =
                    make_float2(__int_as_float((j * 32 + lane) * BATCH), z[j] - tau);
        }
        base += __popc(mm);
    }
    if (base > MAXC) base = MAXC;
    const int pad = (base + 1) & ~1;     // pad to multiple of 2 only
    if (lane < pad - base)
        g_sel[col * MAXC + base + lane] = make_float2(__int_as_float(0), 0.0f);
    if (lane == 0) g_nnz[col] = pad;
}

// ============================================================================
// Kernel 2: gate[col][b] = sparsemoid((sum_j w_j*xT[idx_j][b] - th)*e^{-lt}).
// One block per column (3072 blocks, 256 threads). Thread owns b = 2*tid and
// 2*tid+1 -> ONE float2 LDG per entry (vs two 32-bit), float2 gate store.
// ============================================================================
__global__ void __launch_bounds__(256)
fv_kernel(const float* __restrict__ th,
          const float* __restrict__ lt)
{
    const int col = blockIdx.x;
    const int tid = threadIdx.x;
    const int cnt = g_nnz[col];           // multiple of 2
    const float2* __restrict__ lst = g_sel + col * MAXC;

    const float thv = __ldg(th + col);
    const float etv = __expf(-__ldg(lt + col));

    float f0 = 0.0f, f1 = 0.0f;
    #pragma unroll 1
    for (int j = 0; j < cnt; j += 2) {
        float2 e0 = __ldg(lst + j);
        float2 e1 = __ldg(lst + j + 1);
        float2 a = *(const float2*)(g_xT + __float_as_int(e0.x) + 2 * tid);
        float2 b = *(const float2*)(g_xT + __float_as_int(e1.x) + 2 * tid);
        f0 += e0.y * a.x + e1.y * b.x;
        f1 += e0.y * a.y + e1.y * b.y;
    }
    float2 gv;
    gv.x = __saturatef(0.5f * ((f0 - thv) * etv) + 0.5f);
    gv.y = __saturatef(0.5f * ((f1 - thv) * etv) + 0.5f);
    *(float2*)(g_gate + col * BATCH + 2 * tid) = gv;
}

// ============================================================================
// Kernel 3: tiled forest, 4 batch rows per thread, coalesced output.
// Block = (128-b x 8-n) tile; 256 blocks x 256 threads, 2 blocks/SM (single
// wave). Each resp float4 LDS feeds 4 b's -> 12 LDS.128 per output.
// ============================================================================
__global__ void __launch_bounds__(256, 2)
forest_kernel(const float* __restrict__ resp,  // (NTREES, UNITS, NLEAVES)
              float* __restrict__ out)         // (BATCH, NTREES, UNITS)
{
    const int nt  = blockIdx.x & 63;      // 64 n-tiles
    const int btl = blockIdx.x >> 6;      // 4 b-tiles
    const int n0  = nt * NT;
    const int b0  = btl * BT;
    const int tid = threadIdx.x;
    const int tx  = tid & 31;             // b_local (first of four)
    const int ty  = tid >> 5;             // n_local, 0..7

    const int n = n0 + ty;

    // issue all 24 gate loads first (independent of smem staging)
    float g[4][DEPTH];
    #pragma unroll
    for (int p = 0; p < 4; p++)
        #pragma unroll
        for (int d = 0; d < DEPTH; d++)
            g[p][d] = g_gate[(n * DEPTH + d) * BATCH + b0 + tx + p * 32];

    __shared__ float4 s_resp[NT * 48];            // 8 trees x 192 floats = 6 KB
    __shared__ float  s_out[BT][NT * UNITS + 1];  // 128 x 25 = 12.5 KB

    s_resp[tid] = ((const float4*)resp)[n0 * 48 + tid];
    if (tid < NT * 48 - 256)
        s_resp[tid + 256] = ((const float4*)resp)[n0 * 48 + tid + 256];
    __syncthreads();

    // leaf prob factorization per b: p_c = qlo[c&7] * qhi[c>>3]
    float qlo[4][8], qhi[4][8];
    #pragma unroll
    for (int p = 0; p < 4; p++) {
        #pragma unroll
        for (int c = 0; c < 8; c++) {
            float a0 = (c & 1) ? (1.0f - g[p][0]) : g[p][0];
            float a1 = (c & 2) ? (1.0f - g[p][1]) : g[p][1];
            float a2 = (c & 4) ? (1.0f - g[p][2]) : g[p][2];
            qlo[p][c] = a0 * a1 * a2;
            float a3 = (c & 1) ? (1.0f - g[p][3]) : g[p][3];
            float a4 = (c & 2) ? (1.0f - g[p][4]) : g[p][4];
            float a5 = (c & 4) ? (1.0f - g[p][5]) : g[p][5];
            qhi[p][c] = a3 * a4 * a5;
        }
    }

    // response contraction: each resp float4 feeds all 4 b's
    float acc[4][UNITS];
    #pragma unroll
    for (int p = 0; p < 4; p++)
        #pragma unroll
        for (int u = 0; u < UNITS; u++) acc[p][u] = 0.0f;

    #pragma unroll
    for (int hi = 0; hi < 8; hi++) {
        #pragma unroll
        for (int u = 0; u < UNITS; u++) {
            float4 ra = s_resp[ty * 48 + (u * NLEAVES + hi * 8) / 4];
            float4 rc = s_resp[ty * 48 + (u * NLEAVES + hi * 8) / 4 + 1];
            #pragma unroll
            for (int p = 0; p < 4; p++) {
                float t = ra.x * qlo[p][0] + ra.y * qlo[p][1]
                        + ra.z * qlo[p][2] + ra.w * qlo[p][3]
                        + rc.x * qlo[p][4] + rc.y * qlo[p][5]
                        + rc.z * qlo[p][6] + rc.w * qlo[p][7];
                acc[p][u] += qhi[p][hi] * t;
            }
        }
    }

    #pragma unroll
    for (int p = 0; p < 4; p++)
        #pragma unroll
        for (int u = 0; u < UNITS; u++)
            s_out[tx + p * 32][ty * UNITS + u] = acc[p][u];
    __syncthreads();

    // coalesced write-out: per-b contiguous 24-float (96 B) runs
    #pragma unroll
    for (int r = 0; r < 12; r++) {
        int i   = tid + r * 256;                 // 0 .. 3071
        int row = i / (NT * UNITS);              // b_local 0..127
        int c   = i % (NT * UNITS);
        out[(size_t)(b0 + row) * (NTREES * UNITS) + n0 * UNITS + c] = s_out[row][c];
    }
}

// ============================================================================
extern "C" void kernel_launch(void* const* d_in, const int* in_sizes, int n_in,
                              void* d_out, int out_size)
{
    const float* x    = (const float*)d_in[0];  // (512, 256)
    const float* fsl  = (const float*)d_in[1];  // (256, 512, 6)
    const float* th   = (const float*)d_in[2];  // (512, 6)
    const float* lt   = (const float*)d_in[3];  // (512, 6)
    const float* resp = (const float*)d_in[4];  // (512, 3, 64)
    float* out = (float*)d_out;                 // (512, 512, 3)

    transpose_kernel<<<896, 256>>>(x, fsl);
    sparsemax_kernel<<<NCOLS / 8, 256>>>();
    fv_kernel<<<NCOLS, 256>>>(th, lt);
    forest_kernel<<<(BATCH / BT) * (NTREES / NT), 256>>>(resp, out);
}

// round 14
// speedup vs baseline: 1.0076x; 1.0076x over previous
#include <cuda_runtime.h>
#include <cuda_bf16.h>
#include <math.h>

// Problem constants
#define BATCH   512
#define DIM     256
#define NTREES  512
#define DEPTH   6
#define UNITS   3
#define NLEAVES 64
#define NCOLS   (NTREES * DEPTH)   // 3072 sparsemax columns
#define MAXC    64                 // max sparsemax support per column (padded)
#define BT      64                 // forest batch tile (2 b per thread) — R12 best
#define NT      8                  // forest tree tile

// -------- device scratch (no dynamic allocation allowed) --------
__device__ float  g_xT[DIM * BATCH];       // transposed x: (DIM, BATCH)
__device__ float  g_fslT[NCOLS * DIM];     // transposed fsl: (col, i)
__device__ int    g_nnz[NCOLS];            // PADDED support size (multiple of 2)
__device__ float2 g_sel[NCOLS * MAXC];     // interleaved (idx*BATCH as int bits, weight)
__device__ float  g_gate[NCOLS * BATCH];   // gate values, layout (col, b)

// ============================================================================
// Kernel 0: float4 tiled transposes. 32x32 tiles, 256 threads:
// 1 LDG.128 + 4 STS + 4 LDS + 1 STG.128 per thread, bank-conflict-free.
//  blocks [0, 768): fsl (256 i, 3072 col) -> fslT (col, i).
//  blocks [768, 896): x (512 b, 256 i)    -> xT (i, b).
// ============================================================================
__global__ void __launch_bounds__(256)
transpose_kernel(const float* __restrict__ x,
                 const float* __restrict__ fsl)
{
    __shared__ float s[32][33];
    const int bid = blockIdx.x;
    const int t   = threadIdx.x;
    const int row = t >> 3;       // 0..31
    const int c4  = t & 7;        // 0..7

    const float* src;
    float*       dst;
    int src_stride, dst_stride, r0_in, c0_in;

    if (bid < 768) {
        const int it = bid / 96;
        const int ct = bid % 96;
        src = fsl;   src_stride = NCOLS;  r0_in = it * 32; c0_in = ct * 32;
        dst = g_fslT; dst_stride = DIM;
    } else {
        const int tt = bid - 768;
        const int bt = tt & 15;
        const int it = tt >> 4;
        src = x;     src_stride = DIM;    r0_in = bt * 32; c0_in = it * 32;
        dst = g_xT;  dst_stride = BATCH;
    }

    float4 v = *(const float4*)(src + (size_t)(r0_in + row) * src_stride + c0_in + c4 * 4);
    s[row][c4 * 4 + 0] = v.x;
    s[row][c4 * 4 + 1] = v.y;
    s[row][c4 * 4 + 2] = v.z;
    s[row][c4 * 4 + 3] = v.w;
    __syncthreads();

    float4 w;
    w.x = s[c4 * 4 + 0][row];
    w.y = s[c4 * 4 + 1][row];
    w.z = s[c4 * 4 + 2][row];
    w.w = s[c4 * 4 + 3][row];
    *(float4*)(dst + (size_t)(c0_in + row) * dst_stride + r0_in + c4 * 4) = w;
}

// ============================================================================
// Kernel 1: sparsemax, one warp per column, coalesced fslT loads.
// 384 blocks x 256 threads, warp-level only. Michelot warm-started at
// tau0 = max(z)-1 (valid: tau* >= zmax-1). Output padded to multiple of 2.
// ============================================================================
__global__ void __launch_bounds__(256)
sparsemax_kernel()
{
    const int warp = threadIdx.x >> 5;
    const int lane = threadIdx.x & 31;
    const int col  = blockIdx.x * 8 + warp;

    float z[8];
    #pragma unroll
    for (int j = 0; j < 8; j++)
        z[j] = g_fslT[col * DIM + j * 32 + lane];

    float m = z[0];
    #pragma unroll
    for (int j = 1; j < 8; j++) m = fmaxf(m, z[j]);
    #pragma unroll
    for (int o = 16; o > 0; o >>= 1)
        m = fmaxf(m, __shfl_xor_sync(0xffffffffu, m, o));
    float tau = m - 1.0f;

    int k_prev = -1;
    #pragma unroll 1
    for (int it = 0; it < 16; it++) {
        float s = 0.0f;
        int   k = 0;
        #pragma unroll
        for (int j = 0; j < 8; j++)
            if (z[j] > tau) { s += z[j]; k++; }
        #pragma unroll
        for (int o = 16; o > 0; o >>= 1)
            s += __shfl_xor_sync(0xffffffffu, s, o);
        k = __reduce_add_sync(0xffffffffu, k);
        if (k == k_prev) break;
        k_prev = k;
        tau = (s - 1.0f) / (float)k;
    }

    int base = 0;
    #pragma unroll
    for (int j = 0; j < 8; j++) {
        const bool nz = (z[j] > tau);
        const unsigned mm = __ballot_sync(0xffffffffu, nz);
        if (nz) {
            int pos = base + __popc(mm & ((1u << lane) - 1u));
            if (pos < MAXC)
                g_sel[col * MAXC + pos] =
                    make_float2(__int_as_float((j * 32 + lane) * BATCH), z[j] - tau);
        }
        base += __popc(mm);
    }
    if (base > MAXC) base = MAXC;
    const int pad = (base + 1) & ~1;     // pad to multiple of 2 only
    if (lane < pad - base)
        g_sel[col * MAXC + base + lane] = make_float2(__int_as_float(0), 0.0f);
    if (lane == 0) g_nnz[col] = pad;
}

// ============================================================================
// Kernel 2: gate[col][b] = sparsemoid((sum_j w_j*xT[idx_j][b] - th)*e^{-lt}).
// One block per column (3072 blocks, 256 threads). Thread owns b = 2*tid and
// 2*tid+1 -> ONE float2 LDG per entry, float2 gate store.  (R13, measured win)
// ============================================================================
__global__ void __launch_bounds__(256)
fv_kernel(const float* __restrict__ th,
          const float* __restrict__ lt)
{
    const int col = blockIdx.x;
    const int tid = threadIdx.x;
    const int cnt = g_nnz[col];           // multiple of 2
    const float2* __restrict__ lst = g_sel + col * MAXC;

    const float thv = __ldg(th + col);
    const float etv = __expf(-__ldg(lt + col));

    float f0 = 0.0f, f1 = 0.0f;
    #pragma unroll 1
    for (int j = 0; j < cnt; j += 2) {
        float2 e0 = __ldg(lst + j);
        float2 e1 = __ldg(lst + j + 1);
        float2 a = *(const float2*)(g_xT + __float_as_int(e0.x) + 2 * tid);
        float2 b = *(const float2*)(g_xT + __float_as_int(e1.x) + 2 * tid);
        f0 += e0.y * a.x + e1.y * b.x;
        f1 += e0.y * a.y + e1.y * b.y;
    }
    float2 gv;
    gv.x = __saturatef(0.5f * ((f0 - thv) * etv) + 0.5f);
    gv.y = __saturatef(0.5f * ((f1 - thv) * etv) + 0.5f);
    *(float2*)(g_gate + col * BATCH + 2 * tid) = gv;
}

// ============================================================================
// Kernel 3: tiled forest, 2 batch rows per thread, coalesced output.  (R12 best)
// Block = (64-b x 8-n) tile; 512 blocks x 256 threads, 4 blocks/SM.
// Each resp float4 LDS feeds BOTH b's.
// ============================================================================
__global__ void __launch_bounds__(256, 4)
forest_kernel(const float* __restrict__ resp,  // (NTREES, UNITS, NLEAVES)
              float* __restrict__ out)         // (BATCH, NTREES, UNITS)
{
    const int nt  = blockIdx.x & 63;      // 64 n-tiles
    const int btl = blockIdx.x >> 6;      // 8 b-tiles
    const int n0  = nt * NT;
    const int b0  = btl * BT;
    const int tid = threadIdx.x;
    const int tx  = tid & 31;             // b_local (first of two)
    const int ty  = tid >> 5;             // n_local, 0..7

    const int b1 = b0 + tx;
    const int n  = n0 + ty;

    // issue all gate loads first (independent of smem staging)
    float ga[DEPTH], gb[DEPTH];
    #pragma unroll
    for (int d = 0; d < DEPTH; d++) {
        ga[d] = g_gate[(n * DEPTH + d) * BATCH + b1];
        gb[d] = g_gate[(n * DEPTH + d) * BATCH + b1 + 32];
    }

    __shared__ float4 s_resp[NT * 48];            // 8 trees x 192 floats = 6 KB
    __shared__ float  s_out[BT][NT * UNITS + 1];  // 64 x 25, conflict-free

    s_resp[tid] = ((const float4*)resp)[n0 * 48 + tid];
    if (tid < NT * 48 - 256)
        s_resp[tid + 256] = ((const float4*)resp)[n0 * 48 + tid + 256];
    __syncthreads();

    // leaf prob factorization for both b's: p_c = qlo[c&7] * qhi[c>>3]
    float qloa[8], qhia[8], qlob[8], qhib[8];
    #pragma unroll
    for (int c = 0; c < 8; c++) {
        float a0 = (c & 1) ? (1.0f - ga[0]) : ga[0];
        float a1 = (c & 2) ? (1.0f - ga[1]) : ga[1];
        float a2 = (c & 4) ? (1.0f - ga[2]) : ga[2];
        qloa[c] = a0 * a1 * a2;
        float a3 = (c & 1) ? (1.0f - ga[3]) : ga[3];
        float a4 = (c & 2) ? (1.0f - ga[4]) : ga[4];
        float a5 = (c & 4) ? (1.0f - ga[5]) : ga[5];
        qhia[c] = a3 * a4 * a5;
        float b0_ = (c & 1) ? (1.0f - gb[0]) : gb[0];
        float b1_ = (c & 2) ? (1.0f - gb[1]) : gb[1];
        float b2_ = (c & 4) ? (1.0f - gb[2]) : gb[2];
        qlob[c] = b0_ * b1_ * b2_;
        float b3_ = (c & 1) ? (1.0f - gb[3]) : gb[3];
        float b4_ = (c & 2) ? (1.0f - gb[4]) : gb[4];
        float b5_ = (c & 4) ? (1.0f - gb[5]) : gb[5];
        qhib[c] = b3_ * b4_ * b5_;
    }

    // response contraction: each resp float4 used by BOTH b's
    float acca[UNITS] = {0.0f, 0.0f, 0.0f};
    float accb[UNITS] = {0.0f, 0.0f, 0.0f};
    #pragma unroll
    for (int hi = 0; hi < 8; hi++) {
        #pragma unroll
        for (int u = 0; u < UNITS; u++) {
            float4 ra = s_resp[ty * 48 + (u * NLEAVES + hi * 8) / 4];
            float4 rc = s_resp[ty * 48 + (u * NLEAVES + hi * 8) / 4 + 1];
            float t1 = ra.x * qloa[0] + ra.y * qloa[1] + ra.z * qloa[2] + ra.w * qloa[3]
                     + rc.x * qloa[4] + rc.y * qloa[5] + rc.z * qloa[6] + rc.w * qloa[7];
            float t2 = ra.x * qlob[0] + ra.y * qlob[1] + ra.z * qlob[2] + ra.w * qlob[3]
                     + rc.x * qlob[4] + rc.y * qlob[5] + rc.z * qlob[6] + rc.w * qlob[7];
            acca[u] += qhia[hi] * t1;
            accb[u] += qhib[hi] * t2;
        }
    }

    #pragma unroll
    for (int u = 0; u < UNITS; u++) {
        s_out[tx][ty * UNITS + u]      = acca[u];
        s_out[tx + 32][ty * UNITS + u] = accb[u];
    }
    __syncthreads();

    // coalesced write-out: per-b contiguous 24-float (96 B) runs
    #pragma unroll
    for (int r = 0; r < 6; r++) {
        int i   = tid + r * 256;                 // 0 .. 1535
        int row = i / (NT * UNITS);              // b_local 0..63
        int c   = i % (NT * UNITS);
        out[(size_t)(b0 + row) * (NTREES * UNITS) + n0 * UNITS + c] = s_out[row][c];
    }
}

// ============================================================================
extern "C" void kernel_launch(void* const* d_in, const int* in_sizes, int n_in,
                              void* d_out, int out_size)
{
    const float* x    = (const float*)d_in[0];  // (512, 256)
    const float* fsl  = (const float*)d_in[1];  // (256, 512, 6)
    const float* th   = (const float*)d_in[2];  // (512, 6)
    const float* lt   = (const float*)d_in[3];  // (512, 6)
    const float* resp = (const float*)d_in[4];  // (512, 3, 64)
    float* out = (float*)d_out;                 // (512, 512, 3)

    transpose_kernel<<<896, 256>>>(x, fsl);
    sparsemax_kernel<<<NCOLS / 8, 256>>>();
    fv_kernel<<<NCOLS, 256>>>(th, lt);
    forest_kernel<<<(BATCH / BT) * (NTREES / NT), 256>>>(resp, out);
}